// round 17
// baseline (speedup 1.0000x reference)
#include <cuda_runtime.h>
#include <cuda_bf16.h>
#include <cstdint>
#include <math.h>

#define L_SEQ   2048
#define DMODEL  1024
#define DINNER  2048
#define DSTATE  64
#define DTRANK  64
#define NBATCH  2
#define NROWS   (NBATCH * L_SEQ)
#define XPAD    256
#define NSPLIT  8

/* -------- scratch (device globals; 256B-aligned for 16B vector access) ---- */
__device__ __align__(256) float g_xz   [(size_t)NROWS * 2 * DINNER];
__device__ __align__(256) float g_xssm [(size_t)NROWS * DINNER];
__device__ __align__(256) float g_xdbl [(size_t)NROWS * XPAD];
__device__ __align__(256) float g_part [(size_t)NSPLIT * NROWS * XPAD];
__device__ __align__(256) float g_dt   [(size_t)NROWS * DINNER];

__device__ __align__(256) __nv_bfloat16 g_uhi [(size_t)NROWS * DMODEL];
__device__ __align__(256) __nv_bfloat16 g_ulo [(size_t)NROWS * DMODEL];
__device__ __align__(256) __nv_bfloat16 g_xhi [(size_t)NROWS * DINNER];
__device__ __align__(256) __nv_bfloat16 g_xlo [(size_t)NROWS * DINNER];
__device__ __align__(256) __nv_bfloat16 g_drhi[(size_t)NROWS * DTRANK];
__device__ __align__(256) __nv_bfloat16 g_drlo[(size_t)NROWS * DTRANK];
__device__ __align__(256) __nv_bfloat16 g_Wihi[(size_t)(2 * DINNER) * DMODEL];
__device__ __align__(256) __nv_bfloat16 g_Wilo[(size_t)(2 * DINNER) * DMODEL];
__device__ __align__(256) __nv_bfloat16 g_Wxhi[(size_t)XPAD * DINNER];
__device__ __align__(256) __nv_bfloat16 g_Wxlo[(size_t)XPAD * DINNER];
__device__ __align__(256) __nv_bfloat16 g_Wdhi[(size_t)DINNER * DTRANK];
__device__ __align__(256) __nv_bfloat16 g_Wdlo[(size_t)DINNER * DTRANK];
__device__ __align__(256) __nv_bfloat16 g_Wohi[(size_t)DMODEL * DINNER];
__device__ __align__(256) __nv_bfloat16 g_Wolo[(size_t)DMODEL * DINNER];
__device__ __align__(256) __nv_bfloat16 g_yhi [(size_t)NROWS * DINNER];
__device__ __align__(256) __nv_bfloat16 g_ylo [(size_t)NROWS * DINNER];

__device__ __forceinline__ void split2(float v, __nv_bfloat16& h, __nv_bfloat16& l)
{
    h = __float2bfloat16(v);
    l = __float2bfloat16(v - __bfloat162float(h));
}

/* ==================== HMMA bf16-split GEMM v4 =============================
 * CTA tile 256x128, 512 threads (16 warps, 4x4, warp tile 64x32).
 * 3-stage cp.async pipeline. ldmatrix fragments.
 * D = Ahi*Bhi + Ahi*Blo + Alo*Bhi, fp32 accum. */
#define HBM 256
#define HBN 128
#define HBK 32
#define HROWB 80
#define HARR_A (HBM * HROWB)                 /* 20480 */
#define HARR_B (HBN * HROWB)                 /* 10240 */
#define HBUF   (2 * HARR_A + 2 * HARR_B)     /* 61440 */
#define HSTAGES 3
#define HSMEM  (HSTAGES * HBUF)              /* 184320 */
#define OFF_AH 0
#define OFF_AL HARR_A
#define OFF_BH (2 * HARR_A)
#define OFF_BL (2 * HARR_A + HARR_B)

enum { EPI_F32 = 0, EPI_SOFTPLUS = 1 };

__device__ __forceinline__ uint32_t smem_u32(const void* p)
{
    uint32_t a;
    asm("{ .reg .u64 t; cvta.to.shared.u64 t, %1; cvt.u32.u64 %0, t; }"
        : "=r"(a) : "l"(p));
    return a;
}
__device__ __forceinline__ void cp16(uint32_t dst, const void* src)
{
    asm volatile("cp.async.cg.shared.global [%0], [%1], 16;"
                 :: "r"(dst), "l"(src));
}
__device__ __forceinline__ void ldsm4(unsigned& r0, unsigned& r1,
                                      unsigned& r2, unsigned& r3, uint32_t addr)
{
    asm volatile("ldmatrix.sync.aligned.m8n8.x4.shared.b16 {%0,%1,%2,%3}, [%4];"
                 : "=r"(r0), "=r"(r1), "=r"(r2), "=r"(r3) : "r"(addr));
}
__device__ __forceinline__ void mma16816(float* c, const unsigned* a,
                                         const unsigned* b)
{
    asm volatile(
        "mma.sync.aligned.m16n8k16.row.col.f32.bf16.bf16.f32 "
        "{%0,%1,%2,%3}, {%4,%5,%6,%7}, {%8,%9}, {%0,%1,%2,%3};"
        : "+f"(c[0]), "+f"(c[1]), "+f"(c[2]), "+f"(c[3])
        : "r"(a[0]), "r"(a[1]), "r"(a[2]), "r"(a[3]), "r"(b[0]), "r"(b[1]));
}
__device__ __forceinline__ float softplusf(float v)
{
    return (v > 20.f) ? v : log1pf(expf(v));
}

template <int EPI>
__global__ __launch_bounds__(512, 1)
void hmma_gemm_kernel(const __nv_bfloat16* __restrict__ Ahi,
                      const __nv_bfloat16* __restrict__ Alo,
                      const __nv_bfloat16* __restrict__ Bhi,
                      const __nv_bfloat16* __restrict__ Blo,
                      float* __restrict__ C, const float* __restrict__ bias,
                      int M, int N, int K)
{
    extern __shared__ __align__(16) char hsm[];
    const uint32_t smb = smem_u32(hsm);

    const int tid  = threadIdx.x;
    const int wid  = tid >> 5;
    const int lane = tid & 31;
    const int wm   = wid & 3;                 /* 4 warps in m (64 rows each) */
    const int wn   = wid >> 2;                /* 4 warps in n (32 cols each) */
    const int m0   = blockIdx.y * HBM;
    const int n0   = blockIdx.x * HBN;
    const int l15  = lane & 15;
    const int lhalf = lane >> 4;

    const int kchunk = K / gridDim.z;
    const int kbeg   = blockIdx.z * kchunk;
    C += (size_t)blockIdx.z * (size_t)M * (size_t)N;

    float acc[4][4][4];
#pragma unroll
    for (int i = 0; i < 4; i++)
#pragma unroll
        for (int j = 0; j < 4; j++)
#pragma unroll
            for (int r = 0; r < 4; r++) acc[i][j][r] = 0.f;

    const int ntiles = kchunk / HBK;

    /* 3072 x 16B chunks per tile: A hi/lo 1024 each, B hi/lo 512 each */
#define PREFETCH(TI, BUF)                                                     \
    do {                                                                      \
        const int kt_ = kbeg + (TI) * HBK;                                    \
        const uint32_t base_ = smb + (uint32_t)(BUF) * HBUF;                  \
        _Pragma("unroll")                                                     \
        for (int it = 0; it < 6; it++) {                                      \
            const int u = tid + it * 512;                                     \
            if (it < 4) {                                                     \
                const int prec  = u >> 10;                                    \
                const int local = u & 1023;                                   \
                const int row   = local >> 2;                                 \
                const int ch    = local & 3;                                  \
                cp16(base_ + (prec ? OFF_AL : OFF_AH) + row * HROWB + ch * 16,\
                     (prec ? Alo : Ahi) + (size_t)(m0 + row) * K + kt_ + ch * 8); \
            } else {                                                          \
                const int v     = u - 2048;                                   \
                const int prec  = v >> 9;                                     \
                const int local = v & 511;                                    \
                const int row   = local >> 2;                                 \
                const int ch    = local & 3;                                  \
                cp16(base_ + (prec ? OFF_BL : OFF_BH) + row * HROWB + ch * 16,\
                     (prec ? Blo : Bhi) + (size_t)(n0 + row) * K + kt_ + ch * 8); \
            }                                                                 \
        }                                                                     \
        asm volatile("cp.async.commit_group;" ::: "memory");                  \
    } while (0)

    PREFETCH(0, 0);
    if (ntiles > 1) PREFETCH(1, 1);

    int buf = 0;
    for (int ti = 0; ti < ntiles; ti++) {
        if (ti + 2 < ntiles) {
            int b2 = buf + 2; if (b2 >= HSTAGES) b2 -= HSTAGES;
            PREFETCH(ti + 2, b2);
            asm volatile("cp.async.wait_group 2;" ::: "memory");
        } else if (ti + 1 < ntiles) {
            asm volatile("cp.async.wait_group 1;" ::: "memory");
        } else {
            asm volatile("cp.async.wait_group 0;" ::: "memory");
        }
        __syncthreads();

        const uint32_t bb = smb + (uint32_t)buf * HBUF;
#pragma unroll
        for (int ks = 0; ks < 2; ks++) {
            const uint32_t kboff = ks * 32 + lhalf * 16;
            unsigned bh[4][2], bl[4][2];
#pragma unroll
            for (int p = 0; p < 2; p++) {
                const uint32_t roff = (uint32_t)(wn * 32 + p * 16 + l15) * HROWB + kboff;
                unsigned r0, r1, r2, r3;
                ldsm4(r0, r1, r2, r3, bb + OFF_BH + roff);
                bh[2 * p][0] = r0; bh[2 * p + 1][0] = r1;
                bh[2 * p][1] = r2; bh[2 * p + 1][1] = r3;
                ldsm4(r0, r1, r2, r3, bb + OFF_BL + roff);
                bl[2 * p][0] = r0; bl[2 * p + 1][0] = r1;
                bl[2 * p][1] = r2; bl[2 * p + 1][1] = r3;
            }
#pragma unroll
            for (int mt = 0; mt < 4; mt++) {
                const uint32_t aoff = (uint32_t)(wm * 64 + mt * 16 + l15) * HROWB + kboff;
                unsigned ah[4], al[4];
                ldsm4(ah[0], ah[1], ah[2], ah[3], bb + OFF_AH + aoff);
                ldsm4(al[0], al[1], al[2], al[3], bb + OFF_AL + aoff);
#pragma unroll
                for (int nt = 0; nt < 4; nt++) mma16816(acc[mt][nt], ah, bh[nt]);
#pragma unroll
                for (int nt = 0; nt < 4; nt++) mma16816(acc[mt][nt], ah, bl[nt]);
#pragma unroll
                for (int nt = 0; nt < 4; nt++) mma16816(acc[mt][nt], al, bh[nt]);
            }
        }
        __syncthreads();
        if (++buf == HSTAGES) buf = 0;
    }

    const int grp = lane >> 2, tig = lane & 3;
#pragma unroll
    for (int mt = 0; mt < 4; mt++) {
        const int row = m0 + wm * 64 + mt * 16 + grp;
#pragma unroll
        for (int nt = 0; nt < 4; nt++) {
            const int col = n0 + wn * 32 + nt * 8 + 2 * tig;
            float v0 = acc[mt][nt][0], v1 = acc[mt][nt][1];
            float v2 = acc[mt][nt][2], v3 = acc[mt][nt][3];
            if (EPI == EPI_SOFTPLUS) {
                const float b0 = bias[col], b1 = bias[col + 1];
                v0 = softplusf(v0 + b0); v1 = softplusf(v1 + b1);
                v2 = softplusf(v2 + b0); v3 = softplusf(v3 + b1);
            }
            *(float2*)&C[(size_t)row * N + col]       = make_float2(v0, v1);
            *(float2*)&C[(size_t)(row + 8) * N + col] = make_float2(v2, v3);
        }
    }
}

/* ---------------- prep kernels -------------------------------------------- */
__global__ __launch_bounds__(256)
void split_kernel(const float* __restrict__ src, __nv_bfloat16* __restrict__ hi,
                  __nv_bfloat16* __restrict__ lo, int n)
{
    int i = blockIdx.x * blockDim.x + threadIdx.x;
    if (i < n) {
        __nv_bfloat16 h, l;
        split2(src[i], h, l);
        hi[i] = h; lo[i] = l;
    }
}

/* W[K,N] fp32 -> W^T[Nout,K] bf16 hi/lo; rows n in [N, Nout) zero-filled */
__global__ __launch_bounds__(256)
void transpose_split_kernel(const float* __restrict__ W,
                            __nv_bfloat16* __restrict__ Thi,
                            __nv_bfloat16* __restrict__ Tlo,
                            int K, int N)
{
    __shared__ float t[32][33];
    const int n0 = blockIdx.x * 32, k0 = blockIdx.y * 32;
    const int tx = threadIdx.x, ty = threadIdx.y;
#pragma unroll
    for (int j = 0; j < 32; j += 8)
        t[ty + j][tx] = (n0 + tx < N)
            ? W[(size_t)(k0 + ty + j) * N + n0 + tx] : 0.f;
    __syncthreads();
#pragma unroll
    for (int j = 0; j < 32; j += 8) {
        const float v = t[tx][ty + j];
        const size_t o = (size_t)(n0 + ty + j) * K + k0 + tx;
        __nv_bfloat16 h, l;
        split2(v, h, l);
        Thi[o] = h; Tlo[o] = l;
    }
}

/* dt_r = x_dbl[:, 0:64] -> bf16 hi/lo [NROWS,64] */
__global__ __launch_bounds__(256)
void dtr_split_kernel(void)
{
    int i = blockIdx.x * blockDim.x + threadIdx.x;
    if (i >= NROWS * DTRANK) return;
    const int row = i >> 6, c = i & (DTRANK - 1);
    __nv_bfloat16 h, l;
    split2(g_xdbl[(size_t)row * XPAD + c], h, l);
    g_drhi[i] = h; g_drlo[i] = l;
}

/* ---------------- reduce NSPLIT split-K partials ------------------------- */
__global__ __launch_bounds__(256)
void reduce_split_kernel(float* __restrict__ dst,
                         const float* __restrict__ src, int n)
{
    int i = blockIdx.x * blockDim.x + threadIdx.x;
    if (i < n) {
        float s = 0.f;
#pragma unroll
        for (int p = 0; p < NSPLIT; p++) s += src[(size_t)p * n + i];
        dst[i] = s;
    }
}

/* -------- causal depthwise conv (K=4) + bias + SiLU; emit f32 + hi/lo ----- */
__global__ __launch_bounds__(256)
void conv_silu_kernel(const float* __restrict__ convw,
                      const float* __restrict__ convb)
{
    int idx = blockIdx.x * blockDim.x + threadIdx.x;
    if (idx >= NROWS * DINNER) return;
    const int d   = idx & (DINNER - 1);
    const int row = idx >> 11;
    const int l   = row & (L_SEQ - 1);
    const int b   = row >> 11;
    float acc = convb[d];
#pragma unroll
    for (int k = 0; k < 4; k++) {
        const int ls = l - 3 + k;
        if (ls >= 0)
            acc = fmaf(convw[d * 4 + k],
                       g_xz[(size_t)(b * L_SEQ + ls) * (2 * DINNER) + d], acc);
    }
    acc = acc / (1.f + __expf(-acc));
    g_xssm[idx] = acc;
    __nv_bfloat16 h, l2;
    split2(acc, h, l2);
    g_xhi[idx] = h; g_xlo[idx] = l2;
}

/* -------- selective scan v1 + fused gate (emit y as bf16 hi/lo) ----------- */
#define SCAN_T 64
#define CPB    8
__global__ __launch_bounds__(256)
void scan_kernel(const float* __restrict__ A_log, const float* __restrict__ Dvec)
{
    __shared__ __align__(8) float sBC[SCAN_T][2 * DSTATE];
    __shared__ float sdt[SCAN_T][CPB];
    __shared__ float sx [SCAN_T][CPB];
    __shared__ float sy [SCAN_T][CPB];
    __shared__ float sD [CPB];

    const int b    = blockIdx.y;
    const int d0   = blockIdx.x * CPB;
    const int tid  = threadIdx.x;
    const int w    = tid >> 5;
    const int lane = tid & 31;
    const int d    = d0 + w;

    if (tid < CPB) sD[tid] = Dvec[d0 + tid];

    const float a0 = -expf(A_log[(size_t)d * DSTATE + 2 * lane]);
    const float a1 = -expf(A_log[(size_t)d * DSTATE + 2 * lane + 1]);
    float h0 = 0.f, h1 = 0.f;
    const int rowbase = b * L_SEQ;

    for (int t0 = 0; t0 < L_SEQ; t0 += SCAN_T) {
        for (int i = tid; i < SCAN_T * 2 * DSTATE; i += 256) {
            const int t = i >> 7, j = i & 127;
            sBC[t][j] = g_xdbl[(size_t)(rowbase + t0 + t) * XPAD + DTRANK + j];
        }
        for (int i = tid; i < SCAN_T * CPB; i += 256) {
            const int t = i / CPB, c = i % CPB;
            const size_t r = (size_t)(rowbase + t0 + t) * DINNER + d0 + c;
            sdt[t][c] = g_dt[r];
            sx [t][c] = g_xssm[r];
        }
        __syncthreads();

        for (int t = 0; t < SCAN_T; t++) {
            const float dtv = sdt[t][w];
            const float xv  = sx [t][w];
            const float2 Bv = *reinterpret_cast<const float2*>(&sBC[t][2 * lane]);
            const float2 Cv = *reinterpret_cast<const float2*>(&sBC[t][DSTATE + 2 * lane]);
            const float dA0 = __expf(a0 * dtv);
            const float dA1 = __expf(a1 * dtv);
            const float dbx = dtv * xv;
            h0 = fmaf(dA0, h0, dbx * Bv.x);
            h1 = fmaf(dA1, h1, dbx * Bv.y);
            float s = fmaf(h1, Cv.y, h0 * Cv.x);
            s += __shfl_xor_sync(0xffffffffu, s, 16);
            s += __shfl_xor_sync(0xffffffffu, s, 8);
            s += __shfl_xor_sync(0xffffffffu, s, 4);
            s += __shfl_xor_sync(0xffffffffu, s, 2);
            s += __shfl_xor_sync(0xffffffffu, s, 1);
            if (lane == 0) sy[t][w] = s;
        }
        __syncthreads();

        for (int i = tid; i < SCAN_T * CPB; i += 256) {
            const int t = i / CPB, c = i % CPB;
            const int rr = rowbase + t0 + t;
            const float z = g_xz[(size_t)rr * (2 * DINNER) + DINNER + d0 + c];
            const float v = (sy[t][c] + sx[t][c] * sD[c]) *
                            (z / (1.f + __expf(-z)));
            __nv_bfloat16 h, l;
            split2(v, h, l);
            const size_t o = (size_t)rr * DINNER + d0 + c;
            g_yhi[o] = h; g_ylo[o] = l;
        }
        __syncthreads();
    }
}

/* ---------------- host orchestration -------------------------------------- */
extern "C" void kernel_launch(void* const* d_in, const int* in_sizes, int n_in,
                              void* d_out, int out_size)
{
    const float* u     = (const float*)d_in[0];
    const float* W_in  = (const float*)d_in[1];
    const float* convw = (const float*)d_in[2];
    const float* convb = (const float*)d_in[3];
    const float* W_x   = (const float*)d_in[4];
    const float* W_dt  = (const float*)d_in[5];
    const float* b_dt  = (const float*)d_in[6];
    const float* A_log = (const float*)d_in[7];
    const float* Dvec  = (const float*)d_in[8];
    const float* W_out = (const float*)d_in[9];
    float* out = (float*)d_out;

    void* p;
    cudaGetSymbolAddress(&p, g_xz);    float* xz   = (float*)p;
    cudaGetSymbolAddress(&p, g_xdbl);  float* xdbl = (float*)p;
    cudaGetSymbolAddress(&p, g_part);  float* part = (float*)p;
    cudaGetSymbolAddress(&p, g_dt);    float* dtb  = (float*)p;
    cudaGetSymbolAddress(&p, g_uhi);   __nv_bfloat16* uhi  = (__nv_bfloat16*)p;
    cudaGetSymbolAddress(&p, g_ulo);   __nv_bfloat16* ulo  = (__nv_bfloat16*)p;
    cudaGetSymbolAddress(&p, g_xhi);   __nv_bfloat16* xhi  = (__nv_bfloat16*)p;
    cudaGetSymbolAddress(&p, g_xlo);   __nv_bfloat16* xlo  = (__nv_bfloat16*)p;
    cudaGetSymbolAddress(&p, g_drhi);  __nv_bfloat16* drhi = (__nv_bfloat16*)p;
    cudaGetSymbolAddress(&p, g_drlo);  __nv_bfloat16* drlo = (__nv_bfloat16*)p;
    cudaGetSymbolAddress(&p, g_Wihi);  __nv_bfloat16* wihi = (__nv_bfloat16*)p;
    cudaGetSymbolAddress(&p, g_Wilo);  __nv_bfloat16* wilo = (__nv_bfloat16*)p;
    cudaGetSymbolAddress(&p, g_Wxhi);  __nv_bfloat16* wxhi = (__nv_bfloat16*)p;
    cudaGetSymbolAddress(&p, g_Wxlo);  __nv_bfloat16* wxlo = (__nv_bfloat16*)p;
    cudaGetSymbolAddress(&p, g_Wdhi);  __nv_bfloat16* wdhi = (__nv_bfloat16*)p;
    cudaGetSymbolAddress(&p, g_Wdlo);  __nv_bfloat16* wdlo = (__nv_bfloat16*)p;
    cudaGetSymbolAddress(&p, g_Wohi);  __nv_bfloat16* wohi = (__nv_bfloat16*)p;
    cudaGetSymbolAddress(&p, g_Wolo);  __nv_bfloat16* wolo = (__nv_bfloat16*)p;
    cudaGetSymbolAddress(&p, g_yhi);   __nv_bfloat16* yhi  = (__nv_bfloat16*)p;
    cudaGetSymbolAddress(&p, g_ylo);   __nv_bfloat16* ylo  = (__nv_bfloat16*)p;

    cudaFuncSetAttribute(hmma_gemm_kernel<EPI_F32>,
                         cudaFuncAttributeMaxDynamicSharedMemorySize, HSMEM);
    cudaFuncSetAttribute(hmma_gemm_kernel<EPI_SOFTPLUS>,
                         cudaFuncAttributeMaxDynamicSharedMemorySize, HSMEM);

    const int threads = 256;
    const int n_elem  = NROWS * DINNER;

    /* prep: split u; transpose+split W_in, W_out, W_x (pad 192->256), W_dt */
    split_kernel<<<(NROWS * DMODEL) / threads, threads>>>(u, uhi, ulo,
                                                          NROWS * DMODEL);
    transpose_split_kernel<<<dim3((2 * DINNER) / 32, DMODEL / 32), dim3(32, 8)>>>(
        W_in, wihi, wilo, DMODEL, 2 * DINNER);
    transpose_split_kernel<<<dim3(DMODEL / 32, DINNER / 32), dim3(32, 8)>>>(
        W_out, wohi, wolo, DINNER, DMODEL);
    transpose_split_kernel<<<dim3(XPAD / 32, DINNER / 32), dim3(32, 8)>>>(
        W_x, wxhi, wxlo, DINNER, DTRANK + 2 * DSTATE);
    transpose_split_kernel<<<dim3(DINNER / 32, DTRANK / 32), dim3(32, 8)>>>(
        W_dt, wdhi, wdlo, DTRANK, DINNER);

    /* 1. xz = u @ W_in   (HMMA v4) */
    hmma_gemm_kernel<EPI_F32>
        <<<dim3((2 * DINNER) / HBN, NROWS / HBM, 1), 512, HSMEM>>>(
            uhi, ulo, wihi, wilo, xz, nullptr, NROWS, 2 * DINNER, DMODEL);

    /* 2. causal depthwise conv + SiLU -> x_ssm (f32 + bf16 hi/lo) */
    conv_silu_kernel<<<n_elem / threads, threads>>>(convw, convb);

    /* 3. x_dbl = x_ssm @ W_x  (HMMA v4, N padded to 256, split-K=8) */
    hmma_gemm_kernel<EPI_F32>
        <<<dim3(XPAD / HBN, NROWS / HBM, NSPLIT), 512, HSMEM>>>(
            xhi, xlo, wxhi, wxlo, part, nullptr, NROWS, XPAD, DINNER);
    reduce_split_kernel<<<(NROWS * XPAD) / threads, threads>>>(
        xdbl, part, NROWS * XPAD);

    /* 3b. dt_r -> bf16 hi/lo */
    dtr_split_kernel<<<(NROWS * DTRANK) / threads, threads>>>();

    /* 4. dt = softplus(dt_r @ W_dt + b_dt)  (HMMA v4, K=64) */
    hmma_gemm_kernel<EPI_SOFTPLUS>
        <<<dim3(DINNER / HBN, NROWS / HBM, 1), 512, HSMEM>>>(
            drhi, drlo, wdhi, wdlo, dtb, b_dt, NROWS, DINNER, DTRANK);

    /* 5. selective scan v1 + fused gate -> y bf16 hi/lo */
    scan_kernel<<<dim3(DINNER / CPB, NBATCH), threads>>>(A_log, Dvec);

    /* 6. out = y @ W_out  (HMMA v4) */
    hmma_gemm_kernel<EPI_F32>
        <<<dim3(DMODEL / HBN, NROWS / HBM, 1), 512, HSMEM>>>(
            yhi, ylo, wohi, wolo, out, nullptr, NROWS, DMODEL, DINNER);
}